// round 1
// baseline (speedup 1.0000x reference)
#include <cuda_runtime.h>
#include <cuda_bf16.h>
#include <math.h>
#include <float.h>

// ---------------------------------------------------------------------------
// Problem constants
// ---------------------------------------------------------------------------
#define Bq    4
#define Tq    12
#define Nq    200
#define Cq    64
#define ATTq  128
#define OUTFq 128
#define PREDq 12
#define Mq    600           // 3*N window
#define BW0   40            // B*(T-2)
#define BW1   32            // B*(T-4)

enum { F_RELU = 1, F_RELUB = 2, F_SIGMOID = 4 };

// ---------------------------------------------------------------------------
// Static device scratch (no allocations allowed)
// ---------------------------------------------------------------------------
__device__ float g_cur   [BW0 * Mq * Cq];        // 1.536M
__device__ float g_qkv   [BW0 * Mq * 3 * ATTq];  // 9.216M
__device__ float g_scores[BW0 * Mq * Mq];        // 14.4M
__device__ float g_att   [BW0 * Mq * ATTq];      // 3.072M
__device__ float g_node  [Mq * Cq];
__device__ float g_nA    [Mq * Cq];
__device__ float g_nB    [Mq * Cq];
__device__ float g_adj   [Mq * Mq];
__device__ float g_cand0 [BW0 * Nq * Cq];        // layer0 out == layer1 in
__device__ float g_cand1 [BW1 * Nq * Cq];
__device__ float g_d     [Bq * Nq * 8 * Cq];     // (4,200,512)
__device__ float g_o1    [Bq * Nq * OUTFq];      // (4,200,128)

// ---------------------------------------------------------------------------
// Generic tiled GEMM, C = A(MxK) @ B(KxN) [+bias][relu], relu-on-B-load opt.
// 64x64 block tile, 256 threads, 4x4 per thread, K-tile 16. Batched via z.
// ---------------------------------------------------------------------------
__global__ void gemm_nn(const float* __restrict__ A, int lda, long long aBS,
                        const float* __restrict__ B, int ldb, long long bBS,
                        float* __restrict__ Cm, int ldc, long long cBS,
                        int M, int N, int K,
                        const float* __restrict__ bias, int flags)
{
    A  += (long long)blockIdx.z * aBS;
    B  += (long long)blockIdx.z * bBS;
    Cm += (long long)blockIdx.z * cBS;

    __shared__ float As[16][65];
    __shared__ float Bs[16][65];

    const int tid = threadIdx.x;
    const int tm = tid >> 4, tn = tid & 15;
    const int m0 = blockIdx.y * 64, n0 = blockIdx.x * 64;

    const int arow = tid >> 2;           // 0..63 (m)
    const int acol = (tid & 3) * 4;      // 0..12 (k)
    const int bkr  = tid >> 4;           // 0..15 (k)
    const int bnc  = (tid & 15) * 4;     // 0..60 (n)

    float acc[4][4] = {};
    for (int k0 = 0; k0 < K; k0 += 16) {
        {
            const int gm = m0 + arow;
            #pragma unroll
            for (int j = 0; j < 4; ++j) {
                const int gk = k0 + acol + j;
                As[acol + j][arow] =
                    (gm < M && gk < K) ? A[(long long)gm * lda + gk] : 0.f;
            }
        }
        {
            const int gk = k0 + bkr;
            #pragma unroll
            for (int j = 0; j < 4; ++j) {
                const int gn = n0 + bnc + j;
                float v = (gk < K && gn < N) ? B[(long long)gk * ldb + gn] : 0.f;
                if (flags & F_RELUB) v = fmaxf(v, 0.f);
                Bs[bkr][bnc + j] = v;
            }
        }
        __syncthreads();
        #pragma unroll
        for (int kk = 0; kk < 16; ++kk) {
            float a[4], b[4];
            #pragma unroll
            for (int i = 0; i < 4; ++i) a[i] = As[kk][tm * 4 + i];
            #pragma unroll
            for (int j = 0; j < 4; ++j) b[j] = Bs[kk][tn * 4 + j];
            #pragma unroll
            for (int i = 0; i < 4; ++i)
                #pragma unroll
                for (int j = 0; j < 4; ++j)
                    acc[i][j] = fmaf(a[i], b[j], acc[i][j]);
        }
        __syncthreads();
    }
    #pragma unroll
    for (int i = 0; i < 4; ++i) {
        const int gm = m0 + tm * 4 + i;
        if (gm >= M) continue;
        #pragma unroll
        for (int j = 0; j < 4; ++j) {
            const int gn = n0 + tn * 4 + j;
            if (gn >= N) continue;
            float v = acc[i][j];
            if (bias) v += bias[gn];
            if (flags & F_RELU) v = fmaxf(v, 0.f);
            Cm[(long long)gm * ldc + gn] = v;
        }
    }
}

// C = scale * A(MxK) @ B(NxK)^T, optional sigmoid epilogue. Batched via z.
__global__ void gemm_nt(const float* __restrict__ A, int lda, long long aBS,
                        const float* __restrict__ B, int ldb, long long bBS,
                        float* __restrict__ Cm, int ldc, long long cBS,
                        int M, int N, int K, float scale, int flags)
{
    A  += (long long)blockIdx.z * aBS;
    B  += (long long)blockIdx.z * bBS;
    Cm += (long long)blockIdx.z * cBS;

    __shared__ float As[16][65];
    __shared__ float Bs[16][65];

    const int tid = threadIdx.x;
    const int tm = tid >> 4, tn = tid & 15;
    const int m0 = blockIdx.y * 64, n0 = blockIdx.x * 64;

    const int arow = tid >> 2;           // 0..63 (m or n)
    const int acol = (tid & 3) * 4;      // 0..12 (k)

    float acc[4][4] = {};
    for (int k0 = 0; k0 < K; k0 += 16) {
        {
            const int gm = m0 + arow;
            #pragma unroll
            for (int j = 0; j < 4; ++j) {
                const int gk = k0 + acol + j;
                As[acol + j][arow] =
                    (gm < M && gk < K) ? A[(long long)gm * lda + gk] : 0.f;
            }
        }
        {
            const int gn = n0 + arow;
            #pragma unroll
            for (int j = 0; j < 4; ++j) {
                const int gk = k0 + acol + j;
                Bs[acol + j][arow] =
                    (gn < N && gk < K) ? B[(long long)gn * ldb + gk] : 0.f;
            }
        }
        __syncthreads();
        #pragma unroll
        for (int kk = 0; kk < 16; ++kk) {
            float a[4], b[4];
            #pragma unroll
            for (int i = 0; i < 4; ++i) a[i] = As[kk][tm * 4 + i];
            #pragma unroll
            for (int j = 0; j < 4; ++j) b[j] = Bs[kk][tn * 4 + j];
            #pragma unroll
            for (int i = 0; i < 4; ++i)
                #pragma unroll
                for (int j = 0; j < 4; ++j)
                    acc[i][j] = fmaf(a[i], b[j], acc[i][j]);
        }
        __syncthreads();
    }
    #pragma unroll
    for (int i = 0; i < 4; ++i) {
        const int gm = m0 + tm * 4 + i;
        if (gm >= M) continue;
        #pragma unroll
        for (int j = 0; j < 4; ++j) {
            const int gn = n0 + tn * 4 + j;
            if (gn >= N) continue;
            float v = acc[i][j] * scale;
            if (flags & F_SIGMOID) v = 1.f / (1.f + __expf(-v));
            Cm[(long long)gm * ldc + gn] = v;
        }
    }
}

// ---------------------------------------------------------------------------
// Fused softmax * adj / (sum + 1e-8) * mask, one block per attention row.
// ---------------------------------------------------------------------------
__global__ void softmax_adj_kernel(float* __restrict__ scores,
                                   const float* __restrict__ adj)
{
    const int rowg = blockIdx.x;
    const int m = rowg % Mq;
    float* s = scores + (long long)rowg * Mq;
    const float* arow = adj + (long long)m * Mq;

    __shared__ float p[Mq];
    __shared__ float red[256];
    const int tid = threadIdx.x;

    float mx = -FLT_MAX;
    for (int n = tid; n < Mq; n += 256) mx = fmaxf(mx, s[n]);
    red[tid] = mx; __syncthreads();
    for (int st = 128; st > 0; st >>= 1) {
        if (tid < st) red[tid] = fmaxf(red[tid], red[tid + st]);
        __syncthreads();
    }
    mx = red[0]; __syncthreads();

    float z = 0.f;
    for (int n = tid; n < Mq; n += 256) {
        const float e = __expf(s[n] - mx);
        p[n] = e; z += e;
    }
    red[tid] = z; __syncthreads();
    for (int st = 128; st > 0; st >>= 1) {
        if (tid < st) red[tid] += red[tid + st];
        __syncthreads();
    }
    const float zinv = 1.f / red[0]; __syncthreads();

    float ss = 0.f;
    for (int n = tid; n < Mq; n += 256) {
        const float a = p[n] * zinv * arow[n];
        p[n] = a; ss += a;
    }
    red[tid] = ss; __syncthreads();
    for (int st = 128; st > 0; st >>= 1) {
        if (tid < st) red[tid] += red[tid + st];
        __syncthreads();
    }
    const float ssum = red[0];
    const float inv = (ssum > 0.f) ? 1.f / (ssum + 1e-8f) : 0.f;
    for (int n = tid; n < Mq; n += 256) s[n] = p[n] * inv;
}

// ---------------------------------------------------------------------------
// Elementwise helper kernels
// ---------------------------------------------------------------------------
__global__ void build_windows_kernel(const float* __restrict__ src,
                                     const float* __restrict__ temb,
                                     const float* __restrict__ semb,
                                     float* __restrict__ dst,
                                     int nw, int Tt)
{
    const long long total = (long long)Bq * nw * Mq * Cq;
    long long idx = (long long)blockIdx.x * blockDim.x + threadIdx.x;
    if (idx >= total) return;
    const int c = idx & (Cq - 1);
    long long r = idx >> 6;
    const int j = (int)(r % Mq); r /= Mq;
    const int w = (int)(r % nw);
    const int b = (int)(r / nw);
    const int win = j / Nq, n = j % Nq;
    const int t = w + win;
    dst[idx] = src[(((long long)b * Tt + t) * Nq + n) * Cq + c]
             + temb[t * Cq + c] + semb[n * Cq + c];
}

__global__ void node_mean_kernel(const float* __restrict__ cur,
                                 float* __restrict__ node, int BW)
{
    const int m = blockIdx.x;
    const int c = threadIdx.x;
    float s = 0.f;
    for (int bw = 0; bw < BW; ++bw)
        s += cur[((long long)bw * Mq + m) * Cq + c];
    node[m * Cq + c] = s / (float)BW;
}

__global__ void fill_kernel(float* __restrict__ p, int n, float v)
{
    const int i = blockIdx.x * blockDim.x + threadIdx.x;
    if (i < n) p[i] = v;
}

__global__ void candmax_kernel(float* __restrict__ cand,
                               const float* __restrict__ cur, int BW)
{
    const int total = BW * Nq * Cq;
    const int idx = blockIdx.x * blockDim.x + threadIdx.x;
    if (idx >= total) return;
    const int c = idx & (Cq - 1);
    int r = idx >> 6;
    const int n = r % Nq;
    const int bw = r / Nq;
    const float v = cur[((long long)bw * Mq + 2 * Nq + n) * Cq + c];
    cand[idx] = fmaxf(cand[idx], v);
}

__global__ void transp_kernel(const float* __restrict__ h,
                              float* __restrict__ d)
{
    // h: (4,8,200,64) -> d: (4,200,8*64)
    const int total = Bq * Nq * 8 * Cq;
    const int idx = blockIdx.x * blockDim.x + threadIdx.x;
    if (idx >= total) return;
    const int f = idx & (Cq - 1);
    int r = idx >> 6;
    const int t = r % 8; r /= 8;
    const int n = r % Nq;
    const int b = r / Nq;
    d[idx] = h[(((long long)b * 8 + t) * Nq + n) * Cq + f];
}

__global__ void tile_kernel(const float* __restrict__ o1,
                            float* __restrict__ out)
{
    const int total = Bq * PREDq * Nq * OUTFq;
    const int idx = blockIdx.x * blockDim.x + threadIdx.x;
    if (idx >= total) return;
    const int f = idx & (OUTFq - 1);
    int r = idx >> 7;
    const int row = r % (PREDq * Nq);
    const int b = r / (PREDq * Nq);
    const int n = row % Nq;
    out[idx] = o1[((long long)b * Nq + n) * OUTFq + f];
}

// ---------------------------------------------------------------------------
// Driver
// ---------------------------------------------------------------------------
static inline dim3 gemm_grid(int M, int N, int batch)
{
    return dim3((N + 63) / 64, (M + 63) / 64, batch);
}

extern "C" void kernel_launch(void* const* d_in, const int* in_sizes, int n_in,
                              void* d_out, int out_size)
{
    (void)in_sizes; (void)n_in; (void)out_size;

    const float* x     = (const float*)d_in[0];
    const float* Wqkv  = (const float*)d_in[4];
    const float* bqkv  = (const float*)d_in[5];
    const float* Wlin  = (const float*)d_in[6];
    const float* blin  = (const float*)d_in[7];
    const float* Wa    = (const float*)d_in[8];
    const float* Wb    = (const float*)d_in[9];
    const float* temb0 = (const float*)d_in[13];
    const float* temb1 = (const float*)d_in[14];
    const float* semb  = (const float*)d_in[15];
    const float* Wo    = (const float*)d_in[16];
    const float* bo    = (const float*)d_in[17];
    float* out = (float*)d_out;

    float *cur, *qkv, *scores, *att, *node, *nA, *nB, *adj,
          *cand0, *cand1, *dbuf, *o1;
    cudaGetSymbolAddress((void**)&cur,    g_cur);
    cudaGetSymbolAddress((void**)&qkv,    g_qkv);
    cudaGetSymbolAddress((void**)&scores, g_scores);
    cudaGetSymbolAddress((void**)&att,    g_att);
    cudaGetSymbolAddress((void**)&node,   g_node);
    cudaGetSymbolAddress((void**)&nA,     g_nA);
    cudaGetSymbolAddress((void**)&nB,     g_nB);
    cudaGetSymbolAddress((void**)&adj,    g_adj);
    cudaGetSymbolAddress((void**)&cand0,  g_cand0);
    cudaGetSymbolAddress((void**)&cand1,  g_cand1);
    cudaGetSymbolAddress((void**)&dbuf,   g_d);
    cudaGetSymbolAddress((void**)&o1,     g_o1);

    const float att_scale = 1.0f / sqrtf((float)ATTq);
    const float adj_scale = 1.0f / sqrtf(64.0f);

    for (int layer = 0; layer < 2; ++layer) {
        const int Tt = layer ? (Tq - 2) : Tq;
        const int nw = Tt - 2;
        const int BW = Bq * nw;
        const float* src  = layer ? cand0 : x;
        const float* temb = layer ? temb1 : temb0;
        float* cand = layer ? cand1 : cand0;

        {
            const long long tot = (long long)BW * Mq * Cq;
            build_windows_kernel<<<(unsigned)((tot + 255) / 256), 256>>>(
                src, temb, semb, cur, nw, Tt);
        }
        {
            const int tot = BW * Nq * Cq;
            fill_kernel<<<(tot + 255) / 256, 256>>>(cand, tot, -FLT_MAX);
        }

        for (int f = 0; f < 3; ++f) {
            // --- adjacency ---
            node_mean_kernel<<<Mq, Cq>>>(cur, node, BW);
            gemm_nn<<<gemm_grid(Mq, Cq, 1), 256>>>(
                node, Cq, 0, Wa, Cq, 0, nA, Cq, 0, Mq, Cq, Cq, nullptr, 0);
            gemm_nn<<<gemm_grid(Mq, Cq, 1), 256>>>(
                node, Cq, 0, Wb, Cq, 0, nB, Cq, 0, Mq, Cq, Cq, nullptr, 0);
            gemm_nt<<<gemm_grid(Mq, Mq, 1), 256>>>(
                nA, Cq, 0, nB, Cq, 0, adj, Mq, 0, Mq, Mq, Cq,
                adj_scale, F_SIGMOID);

            // --- qkv projection ---
            gemm_nn<<<gemm_grid(BW * Mq, 3 * ATTq, 1), 256>>>(
                cur, Cq, 0, Wqkv, 3 * ATTq, 0, qkv, 3 * ATTq, 0,
                BW * Mq, 3 * ATTq, Cq, bqkv, 0);

            // --- scores = q @ k^T / sqrt(ATT), batched ---
            gemm_nt<<<gemm_grid(Mq, Mq, BW), 256>>>(
                qkv, 3 * ATTq, (long long)Mq * 3 * ATTq,
                qkv + ATTq, 3 * ATTq, (long long)Mq * 3 * ATTq,
                scores, Mq, (long long)Mq * Mq,
                Mq, Mq, ATTq, att_scale, 0);

            // --- softmax * adj renormalize (in-place -> w) ---
            softmax_adj_kernel<<<BW * Mq, 256>>>(scores, adj);

            // --- att = w @ relu(v), batched ---
            gemm_nn<<<gemm_grid(Mq, ATTq, BW), 256>>>(
                scores, Mq, (long long)Mq * Mq,
                qkv + 2 * ATTq, 3 * ATTq, (long long)Mq * 3 * ATTq,
                att, ATTq, (long long)Mq * ATTq,
                Mq, ATTq, Mq, nullptr, F_RELUB);

            // --- cur = att @ Wlin + blin ---
            gemm_nn<<<gemm_grid(BW * Mq, Cq, 1), 256>>>(
                att, ATTq, 0, Wlin, Cq, 0, cur, Cq, 0,
                BW * Mq, Cq, ATTq, blin, 0);

            // --- candidate max over middle N vertices ---
            {
                const int tot = BW * Nq * Cq;
                candmax_kernel<<<(tot + 255) / 256, 256>>>(cand, cur, BW);
            }
        }
    }

    // --- output layer ---
    {
        const int tot = Bq * Nq * 8 * Cq;
        transp_kernel<<<(tot + 255) / 256, 256>>>(cand1, dbuf);
    }
    gemm_nn<<<gemm_grid(Bq * Nq, OUTFq, 1), 256>>>(
        dbuf, 8 * Cq, 0, Wo, OUTFq, 0, o1, OUTFq, 0,
        Bq * Nq, OUTFq, 8 * Cq, bo, F_RELU);
    {
        const int tot = Bq * PREDq * Nq * OUTFq;
        tile_kernel<<<(tot + 255) / 256, 256>>>(o1, out);
    }
}

// round 2
// speedup vs baseline: 1.2023x; 1.2023x over previous
#include <cuda_runtime.h>
#include <cuda_bf16.h>
#include <math.h>
#include <float.h>

// ---------------------------------------------------------------------------
// Problem constants
// ---------------------------------------------------------------------------
#define Bq    4
#define Tq    12
#define Nq    200
#define Cq    64
#define ATTq  128
#define OUTFq 128
#define PREDq 12
#define Mq    600           // 3*N window
#define BW0   40            // B*(T-2)
#define BW1   32            // B*(T-4)

enum { F_RELU = 1, F_RELUB = 2, F_SIGMOID = 4 };

// ---------------------------------------------------------------------------
// Static device scratch
// ---------------------------------------------------------------------------
__device__ float g_cur   [BW0 * Mq * Cq];
__device__ float g_qkv   [BW0 * Mq * 3 * ATTq];
__device__ float g_scores[BW0 * Mq * Mq];
__device__ float g_att   [BW0 * Mq * ATTq];
__device__ float g_node  [Mq * Cq];
__device__ float g_nA    [Mq * Cq];
__device__ float g_nB    [Mq * Cq];
__device__ float g_adj   [Mq * Mq];
__device__ float g_cand0 [BW0 * Nq * Cq];
__device__ float g_cand1 [BW1 * Nq * Cq];
__device__ float g_d     [Bq * Nq * 8 * Cq];
__device__ float g_o1    [Bq * Nq * OUTFq];

// ---------------------------------------------------------------------------
// Packed f32x2 FMA (SASS FFMA2) — 2x fp32 FMA throughput per issue slot
// ---------------------------------------------------------------------------
__device__ __forceinline__ float2 ffma2(float2 a, float2 b, float2 c)
{
    float2 d;
    asm("fma.rn.f32x2 %0, %1, %2, %3;"
        : "=l"(reinterpret_cast<unsigned long long&>(d))
        : "l"(reinterpret_cast<unsigned long long&>(a)),
          "l"(reinterpret_cast<unsigned long long&>(b)),
          "l"(reinterpret_cast<unsigned long long&>(c)));
    return d;
}

// ---------------------------------------------------------------------------
// Fast GEMM: C = epilogue(scale * A @ op(B) + bias)
//   TB=false: B is (K x N) row-major.   TB=true: B is (N x K) row-major (B^T).
// Block tile 128(M) x 64(N), BK=16, 128 threads, 8x8 micro-tile (m-packed f32x2),
// double-buffered shared, B duplicated in shared for splat-free FFMA2.
// ---------------------------------------------------------------------------
template<bool TB>
__global__ void __launch_bounds__(128, 3)
gemm_fast(const float* __restrict__ A, int lda, long long aBS,
          const float* __restrict__ B, int ldb, long long bBS,
          float* __restrict__ Cm, int ldc, long long cBS,
          int M, int N, int K,
          const float* __restrict__ bias, float scale, int flags)
{
    __shared__ __align__(16) float  As[2][16][128];      // [k][m]
    __shared__ __align__(16) float2 Bs[2][16][8][8];     // [k][j][tn] (dup)

    A  += (long long)blockIdx.z * aBS;
    B  += (long long)blockIdx.z * bBS;
    Cm += (long long)blockIdx.z * cBS;

    const int m0 = blockIdx.y * 128, n0 = blockIdx.x * 64;
    const int tid = threadIdx.x;
    const int tm = tid >> 3, tn = tid & 7;

    float2 acc[4][8];
    #pragma unroll
    for (int i = 0; i < 4; ++i)
        #pragma unroll
        for (int j = 0; j < 8; ++j) acc[i][j] = make_float2(0.f, 0.f);

    const int nk = (K + 15) >> 4;
    const bool relub = (flags & F_RELUB);

    float va[16];
    float vb[8];

    // ---- loaders (global -> regs) ----
    auto loadA = [&](int k0) {
        const int gm = m0 + tid;
        if (gm < M) {
            const float* p = A + (long long)gm * lda + k0;
            if (k0 + 16 <= K) {
                const float4* q = (const float4*)p;
                float4 t0 = q[0], t1 = q[1], t2 = q[2], t3 = q[3];
                va[0]=t0.x; va[1]=t0.y; va[2]=t0.z; va[3]=t0.w;
                va[4]=t1.x; va[5]=t1.y; va[6]=t1.z; va[7]=t1.w;
                va[8]=t2.x; va[9]=t2.y; va[10]=t2.z; va[11]=t2.w;
                va[12]=t3.x; va[13]=t3.y; va[14]=t3.z; va[15]=t3.w;
            } else {
                #pragma unroll
                for (int t = 0; t < 16; ++t)
                    va[t] = (k0 + t < K) ? p[t] : 0.f;
            }
        } else {
            #pragma unroll
            for (int t = 0; t < 16; ++t) va[t] = 0.f;
        }
    };

    auto loadB = [&](int k0) {
        if (!TB) {
            const int kb = tid >> 3, nb = tid & 7;
            const int gk = k0 + kb, gn0 = n0 + nb * 8;
            if (gk < K) {
                const float* p = B + (long long)gk * ldb + gn0;
                if (gn0 + 8 <= N) {
                    const float4* q = (const float4*)p;
                    float4 t0 = q[0], t1 = q[1];
                    vb[0]=t0.x; vb[1]=t0.y; vb[2]=t0.z; vb[3]=t0.w;
                    vb[4]=t1.x; vb[5]=t1.y; vb[6]=t1.z; vb[7]=t1.w;
                } else {
                    #pragma unroll
                    for (int j = 0; j < 8; ++j)
                        vb[j] = (gn0 + j < N) ? p[j] : 0.f;
                }
            } else {
                #pragma unroll
                for (int j = 0; j < 8; ++j) vb[j] = 0.f;
            }
        } else {
            const int nl = tid >> 1, kh = (tid & 1) * 8;
            const int gn = n0 + nl, gk0 = k0 + kh;
            if (gn < N) {
                const float* p = B + (long long)gn * ldb + gk0;
                if (gk0 + 8 <= K) {
                    const float4* q = (const float4*)p;
                    float4 t0 = q[0], t1 = q[1];
                    vb[0]=t0.x; vb[1]=t0.y; vb[2]=t0.z; vb[3]=t0.w;
                    vb[4]=t1.x; vb[5]=t1.y; vb[6]=t1.z; vb[7]=t1.w;
                } else {
                    #pragma unroll
                    for (int t = 0; t < 8; ++t)
                        vb[t] = (gk0 + t < K) ? p[t] : 0.f;
                }
            } else {
                #pragma unroll
                for (int t = 0; t < 8; ++t) vb[t] = 0.f;
            }
        }
    };

    // ---- regs -> shared ----
    auto storeA = [&](int buf) {
        #pragma unroll
        for (int t = 0; t < 16; ++t) As[buf][t][tid] = va[t];
    };
    auto storeB = [&](int buf) {
        if (!TB) {
            const int kb = tid >> 3, nb = tid & 7;
            #pragma unroll
            for (int j = 0; j < 8; ++j) {
                float v = vb[j];
                if (relub) v = fmaxf(v, 0.f);
                Bs[buf][kb][j][nb] = make_float2(v, v);
            }
        } else {
            const int nl = tid >> 1, kh = (tid & 1) * 8;
            const int jj = nl & 7, tt = nl >> 3;
            #pragma unroll
            for (int t = 0; t < 8; ++t) {
                float v = vb[t];
                if (relub) v = fmaxf(v, 0.f);
                Bs[buf][kh + t][jj][tt] = make_float2(v, v);
            }
        }
    };

    // ---- main loop, double-buffered ----
    int buf = 0;
    loadA(0); loadB(0);
    storeA(0); storeB(0);
    __syncthreads();

    for (int t = 0; t < nk; ++t) {
        if (t + 1 < nk) { loadA((t + 1) * 16); loadB((t + 1) * 16); }

        #pragma unroll
        for (int kk = 0; kk < 16; ++kk) {
            const float4* ap = (const float4*)(&As[buf][kk][0]) + tm * 2;
            float4 a0 = ap[0], a1 = ap[1];
            float2 a2[4];
            a2[0] = make_float2(a0.x, a0.y);
            a2[1] = make_float2(a0.z, a0.w);
            a2[2] = make_float2(a1.x, a1.y);
            a2[3] = make_float2(a1.z, a1.w);
            #pragma unroll
            for (int j = 0; j < 8; ++j) {
                float2 b2 = Bs[buf][kk][j][tn];
                #pragma unroll
                for (int i = 0; i < 4; ++i)
                    acc[i][j] = ffma2(a2[i], b2, acc[i][j]);
            }
        }

        if (t + 1 < nk) {
            buf ^= 1;
            storeA(buf); storeB(buf);
        }
        __syncthreads();
    }

    // ---- epilogue + store ----
    auto epi = [&](float v, int gn) {
        v *= scale;
        if (bias) v += bias[gn];
        if (flags & F_RELU) v = fmaxf(v, 0.f);
        if (flags & F_SIGMOID) v = 1.f / (1.f + __expf(-v));
        return v;
    };

    const int gn0 = n0 + tn * 8;
    const bool interior = (gn0 + 8 <= N) && (m0 + tm * 8 + 8 <= M);
    if (interior) {
        #pragma unroll
        for (int i = 0; i < 4; ++i) {
            #pragma unroll
            for (int half = 0; half < 2; ++half) {
                const int gm = m0 + tm * 8 + 2 * i + half;
                float r[8];
                #pragma unroll
                for (int j = 0; j < 8; ++j)
                    r[j] = epi(half ? acc[i][j].y : acc[i][j].x, gn0 + j);
                float4* q = (float4*)(Cm + (long long)gm * ldc + gn0);
                q[0] = make_float4(r[0], r[1], r[2], r[3]);
                q[1] = make_float4(r[4], r[5], r[6], r[7]);
            }
        }
    } else {
        #pragma unroll
        for (int i = 0; i < 4; ++i) {
            #pragma unroll
            for (int half = 0; half < 2; ++half) {
                const int gm = m0 + tm * 8 + 2 * i + half;
                if (gm >= M) continue;
                #pragma unroll
                for (int j = 0; j < 8; ++j) {
                    const int gn = gn0 + j;
                    if (gn >= N) continue;
                    Cm[(long long)gm * ldc + gn] =
                        epi(half ? acc[i][j].y : acc[i][j].x, gn);
                }
            }
        }
    }
}

// ---------------------------------------------------------------------------
// Fused softmax * adj / (sum + 1e-8) * mask, one block per attention row.
// ---------------------------------------------------------------------------
__global__ void softmax_adj_kernel(float* __restrict__ scores,
                                   const float* __restrict__ adj)
{
    const int rowg = blockIdx.x;
    const int m = rowg % Mq;
    float* s = scores + (long long)rowg * Mq;
    const float* arow = adj + (long long)m * Mq;

    __shared__ float p[Mq];
    __shared__ float red[256];
    const int tid = threadIdx.x;

    float mx = -FLT_MAX;
    for (int n = tid; n < Mq; n += 256) mx = fmaxf(mx, s[n]);
    red[tid] = mx; __syncthreads();
    for (int st = 128; st > 0; st >>= 1) {
        if (tid < st) red[tid] = fmaxf(red[tid], red[tid + st]);
        __syncthreads();
    }
    mx = red[0]; __syncthreads();

    float z = 0.f;
    for (int n = tid; n < Mq; n += 256) {
        const float e = __expf(s[n] - mx);
        p[n] = e; z += e;
    }
    red[tid] = z; __syncthreads();
    for (int st = 128; st > 0; st >>= 1) {
        if (tid < st) red[tid] += red[tid + st];
        __syncthreads();
    }
    const float zinv = 1.f / red[0]; __syncthreads();

    float ss = 0.f;
    for (int n = tid; n < Mq; n += 256) {
        const float a = p[n] * zinv * arow[n];
        p[n] = a; ss += a;
    }
    red[tid] = ss; __syncthreads();
    for (int st = 128; st > 0; st >>= 1) {
        if (tid < st) red[tid] += red[tid + st];
        __syncthreads();
    }
    const float ssum = red[0];
    const float inv = (ssum > 0.f) ? 1.f / (ssum + 1e-8f) : 0.f;
    for (int n = tid; n < Mq; n += 256) s[n] = p[n] * inv;
}

// ---------------------------------------------------------------------------
// Elementwise helper kernels
// ---------------------------------------------------------------------------
__global__ void build_windows_kernel(const float* __restrict__ src,
                                     const float* __restrict__ temb,
                                     const float* __restrict__ semb,
                                     float* __restrict__ dst,
                                     int nw, int Tt)
{
    const long long total = (long long)Bq * nw * Mq * Cq;
    long long idx = (long long)blockIdx.x * blockDim.x + threadIdx.x;
    if (idx >= total) return;
    const int c = idx & (Cq - 1);
    long long r = idx >> 6;
    const int j = (int)(r % Mq); r /= Mq;
    const int w = (int)(r % nw);
    const int b = (int)(r / nw);
    const int win = j / Nq, n = j % Nq;
    const int t = w + win;
    dst[idx] = src[(((long long)b * Tt + t) * Nq + n) * Cq + c]
             + temb[t * Cq + c] + semb[n * Cq + c];
}

__global__ void node_mean_kernel(const float* __restrict__ cur,
                                 float* __restrict__ node, int BW)
{
    const int m = blockIdx.x;
    const int c = threadIdx.x;
    float s = 0.f;
    for (int bw = 0; bw < BW; ++bw)
        s += cur[((long long)bw * Mq + m) * Cq + c];
    node[m * Cq + c] = s / (float)BW;
}

__global__ void fill_kernel(float* __restrict__ p, int n, float v)
{
    const int i = blockIdx.x * blockDim.x + threadIdx.x;
    if (i < n) p[i] = v;
}

__global__ void candmax_kernel(float* __restrict__ cand,
                               const float* __restrict__ cur, int BW)
{
    const int total = BW * Nq * Cq;
    const int idx = blockIdx.x * blockDim.x + threadIdx.x;
    if (idx >= total) return;
    const int c = idx & (Cq - 1);
    int r = idx >> 6;
    const int n = r % Nq;
    const int bw = r / Nq;
    const float v = cur[((long long)bw * Mq + 2 * Nq + n) * Cq + c];
    cand[idx] = fmaxf(cand[idx], v);
}

__global__ void transp_kernel(const float* __restrict__ h,
                              float* __restrict__ d)
{
    // h: (4,8,200,64) -> d: (4,200,8*64)
    const int total = Bq * Nq * 8 * Cq;
    const int idx = blockIdx.x * blockDim.x + threadIdx.x;
    if (idx >= total) return;
    const int f = idx & (Cq - 1);
    int r = idx >> 6;
    const int t = r % 8; r /= 8;
    const int n = r % Nq;
    const int b = r / Nq;
    d[idx] = h[(((long long)b * 8 + t) * Nq + n) * Cq + f];
}

__global__ void tile_kernel(const float* __restrict__ o1,
                            float* __restrict__ out)
{
    const int total = Bq * PREDq * Nq * OUTFq;
    const int idx = blockIdx.x * blockDim.x + threadIdx.x;
    if (idx >= total) return;
    const int f = idx & (OUTFq - 1);
    int r = idx >> 7;
    const int row = r % (PREDq * Nq);
    const int b = r / (PREDq * Nq);
    const int n = row % Nq;
    out[idx] = o1[((long long)b * Nq + n) * OUTFq + f];
}

// ---------------------------------------------------------------------------
// Driver
// ---------------------------------------------------------------------------
static inline dim3 fgrid(int M, int N, int batch)
{
    return dim3((N + 63) / 64, (M + 127) / 128, batch);
}

extern "C" void kernel_launch(void* const* d_in, const int* in_sizes, int n_in,
                              void* d_out, int out_size)
{
    (void)in_sizes; (void)n_in; (void)out_size;

    const float* x     = (const float*)d_in[0];
    const float* Wqkv  = (const float*)d_in[4];
    const float* bqkv  = (const float*)d_in[5];
    const float* Wlin  = (const float*)d_in[6];
    const float* blin  = (const float*)d_in[7];
    const float* Wa    = (const float*)d_in[8];
    const float* Wb    = (const float*)d_in[9];
    const float* temb0 = (const float*)d_in[13];
    const float* temb1 = (const float*)d_in[14];
    const float* semb  = (const float*)d_in[15];
    const float* Wo    = (const float*)d_in[16];
    const float* bo    = (const float*)d_in[17];
    float* out = (float*)d_out;

    float *cur, *qkv, *scores, *att, *node, *nA, *nB, *adj,
          *cand0, *cand1, *dbuf, *o1;
    cudaGetSymbolAddress((void**)&cur,    g_cur);
    cudaGetSymbolAddress((void**)&qkv,    g_qkv);
    cudaGetSymbolAddress((void**)&scores, g_scores);
    cudaGetSymbolAddress((void**)&att,    g_att);
    cudaGetSymbolAddress((void**)&node,   g_node);
    cudaGetSymbolAddress((void**)&nA,     g_nA);
    cudaGetSymbolAddress((void**)&nB,     g_nB);
    cudaGetSymbolAddress((void**)&adj,    g_adj);
    cudaGetSymbolAddress((void**)&cand0,  g_cand0);
    cudaGetSymbolAddress((void**)&cand1,  g_cand1);
    cudaGetSymbolAddress((void**)&dbuf,   g_d);
    cudaGetSymbolAddress((void**)&o1,     g_o1);

    const float att_scale = 1.0f / sqrtf((float)ATTq);
    const float adj_scale = 1.0f / 8.0f;   // 1/sqrt(64)

    for (int layer = 0; layer < 2; ++layer) {
        const int Tt = layer ? (Tq - 2) : Tq;
        const int nw = Tt - 2;
        const int BW = Bq * nw;
        const float* src  = layer ? cand0 : x;
        const float* temb = layer ? temb1 : temb0;
        float* cand = layer ? cand1 : cand0;

        {
            const long long tot = (long long)BW * Mq * Cq;
            build_windows_kernel<<<(unsigned)((tot + 255) / 256), 256>>>(
                src, temb, semb, cur, nw, Tt);
        }
        {
            const int tot = BW * Nq * Cq;
            fill_kernel<<<(tot + 255) / 256, 256>>>(cand, tot, -FLT_MAX);
        }

        for (int f = 0; f < 3; ++f) {
            // --- adjacency ---
            node_mean_kernel<<<Mq, Cq>>>(cur, node, BW);
            gemm_fast<false><<<fgrid(Mq, Cq, 1), 128>>>(
                node, Cq, 0, Wa, Cq, 0, nA, Cq, 0,
                Mq, Cq, Cq, nullptr, 1.f, 0);
            gemm_fast<false><<<fgrid(Mq, Cq, 1), 128>>>(
                node, Cq, 0, Wb, Cq, 0, nB, Cq, 0,
                Mq, Cq, Cq, nullptr, 1.f, 0);
            gemm_fast<true><<<fgrid(Mq, Mq, 1), 128>>>(
                nA, Cq, 0, nB, Cq, 0, adj, Mq, 0,
                Mq, Mq, Cq, nullptr, adj_scale, F_SIGMOID);

            // --- qkv projection ---
            gemm_fast<false><<<fgrid(BW * Mq, 3 * ATTq, 1), 128>>>(
                cur, Cq, 0, Wqkv, 3 * ATTq, 0, qkv, 3 * ATTq, 0,
                BW * Mq, 3 * ATTq, Cq, bqkv, 1.f, 0);

            // --- scores = q @ k^T * att_scale, batched ---
            gemm_fast<true><<<fgrid(Mq, Mq, BW), 128>>>(
                qkv, 3 * ATTq, (long long)Mq * 3 * ATTq,
                qkv + ATTq, 3 * ATTq, (long long)Mq * 3 * ATTq,
                scores, Mq, (long long)Mq * Mq,
                Mq, Mq, ATTq, nullptr, att_scale, 0);

            // --- softmax * adj renormalize (in-place -> w) ---
            softmax_adj_kernel<<<BW * Mq, 256>>>(scores, adj);

            // --- att = w @ relu(v), batched ---
            gemm_fast<false><<<fgrid(Mq, ATTq, BW), 128>>>(
                scores, Mq, (long long)Mq * Mq,
                qkv + 2 * ATTq, 3 * ATTq, (long long)Mq * 3 * ATTq,
                att, ATTq, (long long)Mq * ATTq,
                Mq, ATTq, Mq, nullptr, 1.f, F_RELUB);

            // --- cur = att @ Wlin + blin ---
            gemm_fast<false><<<fgrid(BW * Mq, Cq, 1), 128>>>(
                att, ATTq, 0, Wlin, Cq, 0, cur, Cq, 0,
                BW * Mq, Cq, ATTq, blin, 1.f, 0);

            // --- candidate max over middle N vertices ---
            {
                const int tot = BW * Nq * Cq;
                candmax_kernel<<<(tot + 255) / 256, 256>>>(cand, cur, BW);
            }
        }
    }

    // --- output layer ---
    {
        const int tot = Bq * Nq * 8 * Cq;
        transp_kernel<<<(tot + 255) / 256, 256>>>(cand1, dbuf);
    }
    gemm_fast<false><<<fgrid(Bq * Nq, OUTFq, 1), 128>>>(
        dbuf, 8 * Cq, 0, Wo, OUTFq, 0, o1, OUTFq, 0,
        Bq * Nq, OUTFq, 8 * Cq, bo, 1.f, F_RELU);
    {
        const int tot = Bq * PREDq * Nq * OUTFq;
        tile_kernel<<<(tot + 255) / 256, 256>>>(o1, out);
    }
}